// round 1
// baseline (speedup 1.0000x reference)
#include <cuda_runtime.h>
#include <math.h>

#define SEQ   3840
#define DIM   1536
#define NH    12
#define HD    128
#define FG    8
#define HG    20
#define WG    24
#define D_F   22   // rope split: c<22 -> f, c<43 -> h, else w
#define D_FH  43

// ---------------- scratch (device globals; no runtime allocation) -------------
__device__ float g_q[SEQ * DIM];    // q linear -> normed+roped in place (scaled)
__device__ float g_k[SEQ * DIM];    // k linear -> normed+roped in place
__device__ float g_v[SEQ * DIM];    // v linear
__device__ float g_att[SEQ * DIM];  // attention output (pre O-proj)

// ---------------- SGEMM: C[M,N] = A[M,K] @ B[K,N] + bias ---------------------
// 64x64 tile, BK=16, 256 threads, 4x4 per thread. A staged transposed in smem.
__global__ void sgemm64(const float* __restrict__ Ain,
                        const float* __restrict__ B,
                        const float* __restrict__ bias,
                        float* __restrict__ Cin,
                        int M, int N, int K,
                        int asel, int csel)
{
    const float* A = (asel == 0) ? Ain : g_att;
    float* C = (csel == 0) ? g_q : (csel == 1) ? g_k : (csel == 2) ? g_v : Cin;

    __shared__ float As[16 * 64];  // As[k][m]
    __shared__ float Bs[16 * 64];  // Bs[k][n]

    int tid = threadIdx.x;
    int m0 = blockIdx.y * 64, n0 = blockIdx.x * 64;
    int ty = tid / 16, tx = tid % 16;
    int arow = tid >> 2, ak4 = tid & 3;    // A tile: 64 rows x 4 float4
    int brow = tid >> 4, bn4 = tid & 15;   // B tile: 16 rows x 16 float4

    float acc[4][4] = {};

    for (int k0 = 0; k0 < K; k0 += 16) {
        float4 av = *(const float4*)&A[(size_t)(m0 + arow) * K + k0 + ak4 * 4];
        As[(ak4 * 4 + 0) * 64 + arow] = av.x;
        As[(ak4 * 4 + 1) * 64 + arow] = av.y;
        As[(ak4 * 4 + 2) * 64 + arow] = av.z;
        As[(ak4 * 4 + 3) * 64 + arow] = av.w;
        *(float4*)&Bs[brow * 64 + bn4 * 4] =
            *(const float4*)&B[(size_t)(k0 + brow) * N + n0 + bn4 * 4];
        __syncthreads();
#pragma unroll
        for (int kk = 0; kk < 16; kk++) {
            float4 a = *(float4*)&As[kk * 64 + ty * 4];
            float4 b = *(float4*)&Bs[kk * 64 + tx * 4];
            float ar[4] = {a.x, a.y, a.z, a.w};
            float br[4] = {b.x, b.y, b.z, b.w};
#pragma unroll
            for (int i = 0; i < 4; i++)
#pragma unroll
                for (int j = 0; j < 4; j++) acc[i][j] += ar[i] * br[j];
        }
        __syncthreads();
    }

#pragma unroll
    for (int i = 0; i < 4; i++) {
        int r = m0 + ty * 4 + i;
#pragma unroll
        for (int j = 0; j < 4; j++) {
            int cc = n0 + tx * 4 + j;
            C[(size_t)r * N + cc] = acc[i][j] + bias[cc];
        }
    }
}

// ---------------- RMSNorm + RoPE (in place on g_q / g_k) ---------------------
// blockIdx.x = seq pos, blockIdx.y = 0 (q) / 1 (k). Attention scale folded into q.
__global__ void normrope_kernel(const float* __restrict__ nqw,
                                const float* __restrict__ nkw,
                                const float* __restrict__ freqs)
{
    int s = blockIdx.x;
    bool isq = (blockIdx.y == 0);
    float* buf = (isq ? g_q : g_k) + (size_t)s * DIM;
    const float* w = isq ? nqw : nkw;
    float oscale = isq ? 0.08838834764831845f : 1.0f;  // 1/sqrt(128)

    __shared__ float row[DIM];
    __shared__ float red[8];

    int tid = threadIdx.x;
    float ss = 0.f;
    for (int i = tid; i < DIM; i += 256) {
        float v = buf[i];
        row[i] = v;
        ss += v * v;
    }
#pragma unroll
    for (int o = 16; o; o >>= 1) ss += __shfl_xor_sync(0xffffffff, ss, o);
    if ((tid & 31) == 0) red[tid >> 5] = ss;
    __syncthreads();
    if (tid < 8) {
        float t = red[tid];
#pragma unroll
        for (int o = 4; o; o >>= 1) t += __shfl_xor_sync(0xff, t, o);
        if (tid == 0) red[0] = t;
    }
    __syncthreads();
    float r = rsqrtf(red[0] / (float)DIM + 1e-6f);

    int fi = s / (HG * WG);
    int rem = s % (HG * WG);
    int hi = rem / WG;
    int wi = rem % WG;

    for (int p = tid; p < NH * 64; p += 256) {
        int h = p >> 6, c = p & 63;
        int pos = (c < D_F) ? fi : (c < D_FH) ? hi : wi;
        float ang = freqs[pos * 64 + c];
        float sn, cs;
        sincosf(ang, &sn, &cs);
        int j = h * HD + 2 * c;
        float y0 = row[j] * r * w[j];
        float y1 = row[j + 1] * r * w[j + 1];
        buf[j]     = (y0 * cs - y1 * sn) * oscale;
        buf[j + 1] = (y0 * sn + y1 * cs) * oscale;
    }
}

// ---------------- fp32 flash attention ---------------------------------------
// grid: (SEQ/64, NH), 256 threads. Q,K transposed in smem [d][row]; V [row][d].
#define BQ 64
#define BK 64

__global__ void attn_kernel()
{
    extern __shared__ float sm[];
    float* Qs = sm;                 // [128][64] : Qs[d*64 + i]
    float* Ks = Qs + 128 * 64;      // [128][64]
    float* Vs = Ks + 128 * 64;      // [64][128]
    float* Ss = Vs + 64 * 128;      // [64][65]  padded
    float* Ms = Ss + 64 * 65;       // running max
    float* Ls = Ms + 64;            // running denom
    float* Cs = Ls + 64;            // per-tile correction

    int tid = threadIdx.x;
    int h = blockIdx.y;
    int q0 = blockIdx.x * BQ;

    // load Q tile transposed (once)
#pragma unroll
    for (int it = 0; it < 8; it++) {
        int idx = tid + it * 256;        // 2048 float4
        int r = idx & 63, d4 = idx >> 6;
        float4 v = *(const float4*)&g_q[(size_t)(q0 + r) * DIM + h * HD + d4 * 4];
        Qs[(d4 * 4 + 0) * 64 + r] = v.x;
        Qs[(d4 * 4 + 1) * 64 + r] = v.y;
        Qs[(d4 * 4 + 2) * 64 + r] = v.z;
        Qs[(d4 * 4 + 3) * 64 + r] = v.w;
    }

    float Ob[32];
#pragma unroll
    for (int z = 0; z < 32; z++) Ob[z] = 0.f;
    if (tid < 64) { Ms[tid] = -1e30f; Ls[tid] = 0.f; }

    int ty = tid / 16, tx = tid % 16;      // S-phase mapping
    int oi = tid >> 2, og = tid & 3;       // PV mapping: row oi, d in [og*32, og*32+32)

    for (int kb = 0; kb < SEQ / BK; kb++) {
        int k0 = kb * BK;
        __syncthreads();  // previous PV done before overwriting K/V/S

        // K transposed: warp covers 32 rows x const d4 -> conflict-free smem stores
#pragma unroll
        for (int it = 0; it < 8; it++) {
            int idx = tid + it * 256;
            int r = idx & 63, d4 = idx >> 6;
            float4 v = *(const float4*)&g_k[(size_t)(k0 + r) * DIM + h * HD + d4 * 4];
            Ks[(d4 * 4 + 0) * 64 + r] = v.x;
            Ks[(d4 * 4 + 1) * 64 + r] = v.y;
            Ks[(d4 * 4 + 2) * 64 + r] = v.z;
            Ks[(d4 * 4 + 3) * 64 + r] = v.w;
        }
        // V row-major, coalesced
#pragma unroll
        for (int it = 0; it < 8; it++) {
            int idx = tid + it * 256;
            int r = idx >> 5, d4 = idx & 31;
            *(float4*)&Vs[r * 128 + d4 * 4] =
                *(const float4*)&g_v[(size_t)(k0 + r) * DIM + h * HD + d4 * 4];
        }
        __syncthreads();

        // S = Q @ K^T (scale already folded into Q)
        float acc[4][4] = {};
#pragma unroll 4
        for (int d = 0; d < 128; d++) {
            float4 qa = *(float4*)&Qs[d * 64 + ty * 4];
            float4 kb4 = *(float4*)&Ks[d * 64 + tx * 4];
            float qr_[4] = {qa.x, qa.y, qa.z, qa.w};
            float kr_[4] = {kb4.x, kb4.y, kb4.z, kb4.w};
#pragma unroll
            for (int i = 0; i < 4; i++)
#pragma unroll
                for (int j = 0; j < 4; j++) acc[i][j] += qr_[i] * kr_[j];
        }
#pragma unroll
        for (int i = 0; i < 4; i++)
#pragma unroll
            for (int j = 0; j < 4; j++)
                Ss[(ty * 4 + i) * 65 + tx * 4 + j] = acc[i][j];
        __syncthreads();

        // online softmax, one thread per row
        if (tid < 64) {
            float m_old = Ms[tid];
            float mt = m_old;
#pragma unroll 8
            for (int j = 0; j < 64; j++) mt = fmaxf(mt, Ss[tid * 65 + j]);
            float corr = __expf(m_old - mt);
            float lsum = 0.f;
#pragma unroll 8
            for (int j = 0; j < 64; j++) {
                float p = __expf(Ss[tid * 65 + j] - mt);
                Ss[tid * 65 + j] = p;
                lsum += p;
            }
            Ms[tid] = mt;
            Ls[tid] = Ls[tid] * corr + lsum;
            Cs[tid] = corr;
        }
        __syncthreads();

        // O = O*corr + P @ V
        float corr = Cs[oi];
#pragma unroll
        for (int z = 0; z < 32; z++) Ob[z] *= corr;
#pragma unroll 8
        for (int j = 0; j < 64; j++) {
            float p = Ss[oi * 65 + j];
            const float4* vrow = (const float4*)&Vs[j * 128 + og * 32];
#pragma unroll
            for (int z = 0; z < 8; z++) {
                float4 v = vrow[z];
                Ob[z * 4 + 0] += p * v.x;
                Ob[z * 4 + 1] += p * v.y;
                Ob[z * 4 + 2] += p * v.z;
                Ob[z * 4 + 3] += p * v.w;
            }
        }
    }
    __syncthreads();

    float inv = 1.0f / Ls[oi];
    float* dst = &g_att[(size_t)(q0 + oi) * DIM + h * HD + og * 32];
#pragma unroll
    for (int z = 0; z < 8; z++) {
        float4 v;
        v.x = Ob[z * 4 + 0] * inv;
        v.y = Ob[z * 4 + 1] * inv;
        v.z = Ob[z * 4 + 2] * inv;
        v.w = Ob[z * 4 + 3] * inv;
        *(float4*)&dst[z * 4] = v;
    }
}

// ---------------- launch ------------------------------------------------------
extern "C" void kernel_launch(void* const* d_in, const int* in_sizes, int n_in,
                              void* d_out, int out_size)
{
    const float* x    = (const float*)d_in[0];
    const float* q_w  = (const float*)d_in[1];
    const float* q_b  = (const float*)d_in[2];
    const float* k_w  = (const float*)d_in[3];
    const float* k_b  = (const float*)d_in[4];
    const float* v_w  = (const float*)d_in[5];
    const float* v_b  = (const float*)d_in[6];
    const float* o_w  = (const float*)d_in[7];
    const float* o_b  = (const float*)d_in[8];
    const float* nqw  = (const float*)d_in[9];
    const float* nkw  = (const float*)d_in[10];
    const float* freqs = (const float*)d_in[11];
    // d_in[12] = grid_sizes (fixed 8,20,24 — hardcoded)
    float* out = (float*)d_out;

    dim3 gg(DIM / 64, SEQ / 64);

    // QKV projections
    sgemm64<<<gg, 256>>>(x, q_w, q_b, nullptr, SEQ, DIM, DIM, 0, 0);
    sgemm64<<<gg, 256>>>(x, k_w, k_b, nullptr, SEQ, DIM, DIM, 0, 1);
    sgemm64<<<gg, 256>>>(x, v_w, v_b, nullptr, SEQ, DIM, DIM, 0, 2);

    // RMSNorm + RoPE (in place)
    normrope_kernel<<<dim3(SEQ, 2), 256>>>(nqw, nkw, freqs);

    // flash attention
    size_t smem = (size_t)(3 * 64 * 128 + 64 * 65 + 3 * 64) * sizeof(float);
    cudaFuncSetAttribute(attn_kernel, cudaFuncAttributeMaxDynamicSharedMemorySize,
                         (int)smem);
    attn_kernel<<<dim3(SEQ / BQ, NH), 256, smem>>>();

    // output projection
    sgemm64<<<gg, 256>>>(nullptr, o_w, o_b, out, SEQ, DIM, DIM, 1, 3);
}

// round 3
// speedup vs baseline: 3.0978x; 3.0978x over previous
#include <cuda_runtime.h>
#include <math.h>

#define SEQ   3840
#define DIM   1536
#define NH    12
#define HD    128
#define HG    20
#define WG    24
#define D_F   22
#define D_FH  43

// ---------------- scratch (device globals; no runtime allocation) -------------
__device__ float g_q[SEQ * DIM];
__device__ float g_k[SEQ * DIM];
__device__ float g_v[SEQ * DIM];
__device__ float g_att[SEQ * DIM];

// ---------------- packed f32x2 helpers (sm_100+) ------------------------------
typedef unsigned long long u64;

__device__ __forceinline__ u64 fma2(u64 a, u64 b, u64 c) {
    u64 d;
    asm("fma.rn.f32x2 %0, %1, %2, %3;" : "=l"(d) : "l"(a), "l"(b), "l"(c));
    return d;
}
__device__ __forceinline__ u64 mul2(u64 a, u64 b) {
    u64 d;
    asm("mul.rn.f32x2 %0, %1, %2;" : "=l"(d) : "l"(a), "l"(b));
    return d;
}
__device__ __forceinline__ u64 dup2(float a) {
    u64 d;
    asm("mov.b64 %0, {%1, %1};" : "=l"(d) : "f"(a));
    return d;
}
__device__ __forceinline__ float2 unpk(u64 a) {
    float2 f;
    asm("mov.b64 {%0, %1}, %2;" : "=f"(f.x), "=f"(f.y) : "l"(a));
    return f;
}

// ---------------- SGEMM: C[M,N] = A[M,K] @ B[K,N] + bias ----------------------
// 128x128 tile, BK=16, 256 threads, 8x8 per thread via f32x2.
__global__ __launch_bounds__(256, 2)
void sgemm128(const float* __restrict__ Ain,
              const float* __restrict__ B,
              const float* __restrict__ bias,
              float* __restrict__ Cin,
              int asel, int csel)
{
    const int K = DIM, N = DIM;
    const float* A = (asel == 0) ? Ain : g_att;
    float* C = (csel == 0) ? g_q : (csel == 1) ? g_k : (csel == 2) ? g_v : Cin;

    __shared__ float As[16 * 128];   // As[k][m]
    __shared__ float Bs[16 * 128];   // Bs[k][n]

    int tid = threadIdx.x;
    int m0 = blockIdx.y * 128, n0 = blockIdx.x * 128;
    int ty = tid >> 4, tx = tid & 15;

    int ar0 = tid & 127, ac0 = tid >> 7;            // A f4 cols {0,1}
    int ac1 = ac0 + 2;                              // A f4 cols {2,3}
    int bka = tid >> 5, bna = tid & 31;             // B krow 0..7
    int bkb = bka + 8;                              // B krow 8..15

    const float* Ap0 = &A[(size_t)(m0 + ar0) * K + ac0 * 4];
    const float* Ap1 = &A[(size_t)(m0 + ar0) * K + ac1 * 4];
    const float* Bp0 = &B[(size_t)bka * N + n0 + bna * 4];
    const float* Bp1 = &B[(size_t)bkb * N + n0 + bna * 4];

    float4 pa0 = *(const float4*)Ap0;
    float4 pa1 = *(const float4*)Ap1;
    float4 pb0 = *(const float4*)Bp0;
    float4 pb1 = *(const float4*)Bp1;

    u64 acc[8][4];
#pragma unroll
    for (int i = 0; i < 8; i++)
#pragma unroll
        for (int j = 0; j < 4; j++) acc[i][j] = 0ull;

    for (int kt = 0; kt < K / 16; kt++) {
        As[(ac0 * 4 + 0) * 128 + ar0] = pa0.x;
        As[(ac0 * 4 + 1) * 128 + ar0] = pa0.y;
        As[(ac0 * 4 + 2) * 128 + ar0] = pa0.z;
        As[(ac0 * 4 + 3) * 128 + ar0] = pa0.w;
        As[(ac1 * 4 + 0) * 128 + ar0] = pa1.x;
        As[(ac1 * 4 + 1) * 128 + ar0] = pa1.y;
        As[(ac1 * 4 + 2) * 128 + ar0] = pa1.z;
        As[(ac1 * 4 + 3) * 128 + ar0] = pa1.w;
        *(float4*)&Bs[bka * 128 + bna * 4] = pb0;
        *(float4*)&Bs[bkb * 128 + bna * 4] = pb1;
        __syncthreads();

        if (kt + 1 < K / 16) {
            pa0 = *(const float4*)(Ap0 + (kt + 1) * 16);
            pa1 = *(const float4*)(Ap1 + (kt + 1) * 16);
            pb0 = *(const float4*)(Bp0 + (size_t)(kt + 1) * 16 * N);
            pb1 = *(const float4*)(Bp1 + (size_t)(kt + 1) * 16 * N);
        }

#pragma unroll
        for (int k = 0; k < 16; k++) {
            float4 a0 = *(float4*)&As[k * 128 + ty * 8];
            float4 a1 = *(float4*)&As[k * 128 + ty * 8 + 4];
            ulonglong2 bpa = *(ulonglong2*)&Bs[k * 128 + tx * 8];
            ulonglong2 bpb = *(ulonglong2*)&Bs[k * 128 + tx * 8 + 4];
            float av[8] = {a0.x, a0.y, a0.z, a0.w, a1.x, a1.y, a1.z, a1.w};
#pragma unroll
            for (int i = 0; i < 8; i++) {
                u64 ad = dup2(av[i]);
                acc[i][0] = fma2(ad, bpa.x, acc[i][0]);
                acc[i][1] = fma2(ad, bpa.y, acc[i][1]);
                acc[i][2] = fma2(ad, bpb.x, acc[i][2]);
                acc[i][3] = fma2(ad, bpb.y, acc[i][3]);
            }
        }
        __syncthreads();
    }

    float bv[8];
#pragma unroll
    for (int j = 0; j < 8; j++) bv[j] = bias[n0 + tx * 8 + j];
#pragma unroll
    for (int i = 0; i < 8; i++) {
        int row = m0 + ty * 8 + i;
        float2 c0 = unpk(acc[i][0]);
        float2 c1 = unpk(acc[i][1]);
        float2 c2 = unpk(acc[i][2]);
        float2 c3 = unpk(acc[i][3]);
        float4 lo = make_float4(c0.x + bv[0], c0.y + bv[1], c1.x + bv[2], c1.y + bv[3]);
        float4 hi = make_float4(c2.x + bv[4], c2.y + bv[5], c3.x + bv[6], c3.y + bv[7]);
        *(float4*)&C[(size_t)row * N + n0 + tx * 8] = lo;
        *(float4*)&C[(size_t)row * N + n0 + tx * 8 + 4] = hi;
    }
}

// ---------------- RMSNorm + RoPE (in place on g_q / g_k) ----------------------
__global__ void normrope_kernel(const float* __restrict__ nqw,
                                const float* __restrict__ nkw,
                                const float* __restrict__ freqs)
{
    int s = blockIdx.x;
    bool isq = (blockIdx.y == 0);
    float* buf = (isq ? g_q : g_k) + (size_t)s * DIM;
    const float* w = isq ? nqw : nkw;
    float oscale = isq ? 0.08838834764831845f : 1.0f;  // 1/sqrt(128)

    __shared__ float row[DIM];
    __shared__ float red[8];

    int tid = threadIdx.x;
    float ss = 0.f;
    for (int i = tid; i < DIM; i += 256) {
        float v = buf[i];
        row[i] = v;
        ss += v * v;
    }
#pragma unroll
    for (int o = 16; o; o >>= 1) ss += __shfl_xor_sync(0xffffffff, ss, o);
    if ((tid & 31) == 0) red[tid >> 5] = ss;
    __syncthreads();
    if (tid < 8) {
        float t = red[tid];
#pragma unroll
        for (int o = 4; o; o >>= 1) t += __shfl_xor_sync(0xff, t, o);
        if (tid == 0) red[0] = t;
    }
    __syncthreads();
    float r = rsqrtf(red[0] / (float)DIM + 1e-6f);

    int fi = s / (HG * WG);
    int rem = s % (HG * WG);
    int hi = rem / WG;
    int wi = rem % WG;

    for (int p = tid; p < NH * 64; p += 256) {
        int h = p >> 6, c = p & 63;
        int pos = (c < D_F) ? fi : (c < D_FH) ? hi : wi;
        float ang = freqs[pos * 64 + c];
        float sn, cs;
        sincosf(ang, &sn, &cs);
        int j = h * HD + 2 * c;
        float y0 = row[j] * r * w[j];
        float y1 = row[j + 1] * r * w[j + 1];
        buf[j]     = (y0 * cs - y1 * sn) * oscale;
        buf[j + 1] = (y0 * sn + y1 * cs) * oscale;
    }
}

// ---------------- fp32 flash attention, f32x2 ---------------------------------
// grid: (SEQ/128, NH), 256 threads. BQ=128, BK=64.
#define AT_BQ 128
#define AT_BK 64
#define PT_STRIDE 132

__global__ __launch_bounds__(256, 1)
void attn_kernel()
{
    extern __shared__ float sm[];
    float* Qs = sm;                       // 128*128   [d][q]
    float* Ks = Qs + 128 * 128;           // 128*64    [d][k]
    float* Vs = Ks + 128 * 64;            // 64*128    [k][d]
    float* Pt = Vs + 64 * 128;            // 64*132    [k][q]

    int tid = threadIdx.x;
    int h = blockIdx.y;
    int q0 = blockIdx.x * AT_BQ;
    int ty = tid >> 4, tx = tid & 15;

    // load Q tile transposed: 4096 float4
#pragma unroll
    for (int it = 0; it < 16; it++) {
        int idx = tid + it * 256;
        int r = idx & 127, d4 = idx >> 7;
        float4 v = *(const float4*)&g_q[(size_t)(q0 + r) * DIM + h * HD + d4 * 4];
        Qs[(d4 * 4 + 0) * 128 + r] = v.x;
        Qs[(d4 * 4 + 1) * 128 + r] = v.y;
        Qs[(d4 * 4 + 2) * 128 + r] = v.z;
        Qs[(d4 * 4 + 3) * 128 + r] = v.w;
    }

    u64 oacc[8][4];
#pragma unroll
    for (int i = 0; i < 8; i++)
#pragma unroll
        for (int j = 0; j < 4; j++) oacc[i][j] = 0ull;
    float m_run[8], l_run[8];
#pragma unroll
    for (int i = 0; i < 8; i++) { m_run[i] = -1e30f; l_run[i] = 0.f; }

    for (int kb = 0; kb < SEQ / AT_BK; kb++) {
        int k0 = kb * AT_BK;
        __syncthreads();   // previous PV (and Q stores on iter 0) done

        // K transposed: 64 rows x 128 dims = 2048 float4
#pragma unroll
        for (int it = 0; it < 8; it++) {
            int idx = tid + it * 256;
            int r = idx & 63, d4 = idx >> 6;
            float4 v = *(const float4*)&g_k[(size_t)(k0 + r) * DIM + h * HD + d4 * 4];
            Ks[(d4 * 4 + 0) * 64 + r] = v.x;
            Ks[(d4 * 4 + 1) * 64 + r] = v.y;
            Ks[(d4 * 4 + 2) * 64 + r] = v.z;
            Ks[(d4 * 4 + 3) * 64 + r] = v.w;
        }
        // V row-major: 64 rows x 32 float4 = 2048 float4
#pragma unroll
        for (int it = 0; it < 8; it++) {
            int idx = tid + it * 256;
            int r = idx >> 5, d4 = idx & 31;
            *(float4*)&Vs[r * 128 + d4 * 4] =
                *(const float4*)&g_v[(size_t)(k0 + r) * DIM + h * HD + d4 * 4];
        }
        __syncthreads();

        // ---- S = Q @ K^T (scale folded into Q); 8 rows x 4 cols per thread
        u64 sacc[8][2];
#pragma unroll
        for (int i = 0; i < 8; i++) { sacc[i][0] = 0ull; sacc[i][1] = 0ull; }
#pragma unroll 4
        for (int d = 0; d < 128; d++) {
            float4 a0 = *(float4*)&Qs[d * 128 + ty * 8];
            float4 a1 = *(float4*)&Qs[d * 128 + ty * 8 + 4];
            ulonglong2 bp = *(ulonglong2*)&Ks[d * 64 + tx * 4];
            float av[8] = {a0.x, a0.y, a0.z, a0.w, a1.x, a1.y, a1.z, a1.w};
#pragma unroll
            for (int i = 0; i < 8; i++) {
                u64 ad = dup2(av[i]);
                sacc[i][0] = fma2(ad, bp.x, sacc[i][0]);
                sacc[i][1] = fma2(ad, bp.y, sacc[i][1]);
            }
        }

        // ---- online softmax, register-resident (16-lane butterfly per row)
        float p[8][4];
        float corr[8];
#pragma unroll
        for (int i = 0; i < 8; i++) {
            float2 s0 = unpk(sacc[i][0]);
            float2 s1 = unpk(sacc[i][1]);
            p[i][0] = s0.x; p[i][1] = s0.y; p[i][2] = s1.x; p[i][3] = s1.y;
            float mx = fmaxf(fmaxf(p[i][0], p[i][1]), fmaxf(p[i][2], p[i][3]));
#pragma unroll
            for (int o = 8; o; o >>= 1)
                mx = fmaxf(mx, __shfl_xor_sync(0xffffffffu, mx, o));
            float mnew = fmaxf(m_run[i], mx);
            corr[i] = __expf(m_run[i] - mnew);
            float ls = 0.f;
#pragma unroll
            for (int j = 0; j < 4; j++) {
                p[i][j] = __expf(p[i][j] - mnew);
                ls += p[i][j];
            }
#pragma unroll
            for (int o = 8; o; o >>= 1)
                ls += __shfl_xor_sync(0xffffffffu, ls, o);
            l_run[i] = l_run[i] * corr[i] + ls;
            m_run[i] = mnew;
        }
        // write P transposed: Pt[j][row]
#pragma unroll
        for (int c = 0; c < 4; c++) {
            int j = tx * 4 + c;
            float4 lo = make_float4(p[0][c], p[1][c], p[2][c], p[3][c]);
            float4 hi = make_float4(p[4][c], p[5][c], p[6][c], p[7][c]);
            *(float4*)&Pt[j * PT_STRIDE + ty * 8] = lo;
            *(float4*)&Pt[j * PT_STRIDE + ty * 8 + 4] = hi;
        }
        __syncthreads();

        // ---- O = O*corr + P @ V ; 8 rows x 8 cols per thread
#pragma unroll
        for (int i = 0; i < 8; i++) {
            u64 cd = dup2(corr[i]);
#pragma unroll
            for (int jp = 0; jp < 4; jp++) oacc[i][jp] = mul2(oacc[i][jp], cd);
        }
#pragma unroll 2
        for (int j = 0; j < AT_BK; j++) {
            float4 p0 = *(float4*)&Pt[j * PT_STRIDE + ty * 8];
            float4 p1 = *(float4*)&Pt[j * PT_STRIDE + ty * 8 + 4];
            ulonglong2 v0 = *(ulonglong2*)&Vs[j * 128 + tx * 8];
            ulonglong2 v1 = *(ulonglong2*)&Vs[j * 128 + tx * 8 + 4];
            float pv[8] = {p0.x, p0.y, p0.z, p0.w, p1.x, p1.y, p1.z, p1.w};
#pragma unroll
            for (int i = 0; i < 8; i++) {
                u64 ad = dup2(pv[i]);
                oacc[i][0] = fma2(ad, v0.x, oacc[i][0]);
                oacc[i][1] = fma2(ad, v0.y, oacc[i][1]);
                oacc[i][2] = fma2(ad, v1.x, oacc[i][2]);
                oacc[i][3] = fma2(ad, v1.y, oacc[i][3]);
            }
        }
    }

    // ---- final normalize + store
#pragma unroll
    for (int i = 0; i < 8; i++) {
        float inv = 1.0f / l_run[i];
        float2 c0 = unpk(oacc[i][0]);
        float2 c1 = unpk(oacc[i][1]);
        float2 c2 = unpk(oacc[i][2]);
        float2 c3 = unpk(oacc[i][3]);
        float4 lo = make_float4(c0.x * inv, c0.y * inv, c1.x * inv, c1.y * inv);
        float4 hi = make_float4(c2.x * inv, c2.y * inv, c3.x * inv, c3.y * inv);
        float* dst = &g_att[(size_t)(q0 + ty * 8 + i) * DIM + h * HD + tx * 8];
        *(float4*)&dst[0] = lo;
        *(float4*)&dst[4] = hi;
    }
}

// ---------------- launch ------------------------------------------------------
extern "C" void kernel_launch(void* const* d_in, const int* in_sizes, int n_in,
                              void* d_out, int out_size)
{
    const float* x    = (const float*)d_in[0];
    const float* q_w  = (const float*)d_in[1];
    const float* q_b  = (const float*)d_in[2];
    const float* k_w  = (const float*)d_in[3];
    const float* k_b  = (const float*)d_in[4];
    const float* v_w  = (const float*)d_in[5];
    const float* v_b  = (const float*)d_in[6];
    const float* o_w  = (const float*)d_in[7];
    const float* o_b  = (const float*)d_in[8];
    const float* nqw  = (const float*)d_in[9];
    const float* nkw  = (const float*)d_in[10];
    const float* freqs = (const float*)d_in[11];
    float* out = (float*)d_out;

    dim3 gg(DIM / 128, SEQ / 128);

    sgemm128<<<gg, 256>>>(x, q_w, q_b, nullptr, 0, 0);
    sgemm128<<<gg, 256>>>(x, k_w, k_b, nullptr, 0, 1);
    sgemm128<<<gg, 256>>>(x, v_w, v_b, nullptr, 0, 2);

    normrope_kernel<<<dim3(SEQ, 2), 256>>>(nqw, nkw, freqs);

    size_t smem = (size_t)(128 * 128 + 128 * 64 + 64 * 128 + 64 * PT_STRIDE) * sizeof(float);
    cudaFuncSetAttribute(attn_kernel, cudaFuncAttributeMaxDynamicSharedMemorySize,
                         (int)smem);
    attn_kernel<<<dim3(SEQ / AT_BQ, NH), 256, smem>>>();

    sgemm128<<<gg, 256>>>(nullptr, o_w, o_b, out, 1, 3);
}

// round 5
// speedup vs baseline: 4.1037x; 1.3247x over previous
#include <cuda_runtime.h>
#include <cuda_bf16.h>
#include <math.h>
#include <stdint.h>

#define SEQ   3840
#define DIM   1536
#define NH    12
#define HD    128
#define HG    20
#define WG    24
#define D_F   22
#define D_FH  43

typedef unsigned long long u64;

// ---------------- scratch (device globals; no runtime allocation) -------------
__device__ float g_q[SEQ * DIM];
__device__ float g_k[SEQ * DIM];
__device__ float g_v[SEQ * DIM];
__device__ float g_att[SEQ * DIM];

__device__ __nv_bfloat16 g_xh[SEQ * DIM], g_xl[SEQ * DIM];       // x split
__device__ __nv_bfloat16 g_ah[SEQ * DIM], g_al[SEQ * DIM];       // att split
__device__ __nv_bfloat16 g_wh[4][DIM * DIM], g_wl[4][DIM * DIM]; // W^T splits

// ---------------- f32x2 helpers (for SIMT attention) --------------------------
__device__ __forceinline__ u64 fma2(u64 a, u64 b, u64 c) {
    u64 d;
    asm("fma.rn.f32x2 %0, %1, %2, %3;" : "=l"(d) : "l"(a), "l"(b), "l"(c));
    return d;
}
__device__ __forceinline__ u64 mul2(u64 a, u64 b) {
    u64 d;
    asm("mul.rn.f32x2 %0, %1, %2;" : "=l"(d) : "l"(a), "l"(b));
    return d;
}
__device__ __forceinline__ u64 dup2(float a) {
    u64 d;
    asm("mov.b64 %0, {%1, %1};" : "=l"(d) : "f"(a));
    return d;
}
__device__ __forceinline__ float2 unpk(u64 a) {
    float2 f;
    asm("mov.b64 {%0, %1}, %2;" : "=f"(f.x), "=f"(f.y) : "l"(a));
    return f;
}

// ---------------- cp.async helpers --------------------------------------------
__device__ __forceinline__ uint32_t smem_u32(const void* p) {
    uint32_t a;
    asm("{ .reg .u64 t; cvta.to.shared.u64 t, %1; cvt.u32.u64 %0, t; }"
        : "=r"(a) : "l"(p));
    return a;
}
__device__ __forceinline__ void cpasync16(uint32_t saddr, const void* g) {
    asm volatile("cp.async.cg.shared.global [%0], [%1], 16;"
                 :: "r"(saddr), "l"(g) : "memory");
}
#define CP_COMMIT() asm volatile("cp.async.commit_group;" ::: "memory")
#define CP_WAIT0()  asm volatile("cp.async.wait_group 0;" ::: "memory")

// ---------------- mma.sync m16n8k16 bf16 --------------------------------------
__device__ __forceinline__ void mma16816(float& d0, float& d1, float& d2, float& d3,
                                         uint32_t a0, uint32_t a1, uint32_t a2,
                                         uint32_t a3, uint32_t b0, uint32_t b1) {
    asm volatile(
        "mma.sync.aligned.m16n8k16.row.col.f32.bf16.bf16.f32 "
        "{%0,%1,%2,%3}, {%4,%5,%6,%7}, {%8,%9}, {%0,%1,%2,%3};"
        : "+f"(d0), "+f"(d1), "+f"(d2), "+f"(d3)
        : "r"(a0), "r"(a1), "r"(a2), "r"(a3), "r"(b0), "r"(b1));
}

// ---------------- prep: split activations into bf16 hi/lo ---------------------
__global__ void split_act(const float* __restrict__ xsrc, int which)
{
    const float* src = (which == 0) ? xsrc : g_att;
    __nv_bfloat16* dh = (which == 0) ? g_xh : g_ah;
    __nv_bfloat16* dl = (which == 0) ? g_xl : g_al;
    int i = (blockIdx.x * 256 + threadIdx.x) * 4;
    float4 v = *(const float4*)&src[i];
    __nv_bfloat16 h0 = __float2bfloat16(v.x), h1 = __float2bfloat16(v.y);
    __nv_bfloat16 h2 = __float2bfloat16(v.z), h3 = __float2bfloat16(v.w);
    __nv_bfloat16 l0 = __float2bfloat16(v.x - __bfloat162float(h0));
    __nv_bfloat16 l1 = __float2bfloat16(v.y - __bfloat162float(h1));
    __nv_bfloat16 l2 = __float2bfloat16(v.z - __bfloat162float(h2));
    __nv_bfloat16 l3 = __float2bfloat16(v.w - __bfloat162float(h3));
    ushort4 hh, ll;
    hh.x = *(unsigned short*)&h0; hh.y = *(unsigned short*)&h1;
    hh.z = *(unsigned short*)&h2; hh.w = *(unsigned short*)&h3;
    ll.x = *(unsigned short*)&l0; ll.y = *(unsigned short*)&l1;
    ll.z = *(unsigned short*)&l2; ll.w = *(unsigned short*)&l3;
    *(ushort4*)&dh[i] = hh;
    *(ushort4*)&dl[i] = ll;
}

// ---------------- prep: transpose + split weights ------------------------------
// in: W[K][N] f32;  out: g_wh/g_wl[z][N][K] bf16
__global__ void transpose_split(const float* __restrict__ w0,
                                const float* __restrict__ w1,
                                const float* __restrict__ w2,
                                const float* __restrict__ w3)
{
    const float* W = (blockIdx.z == 0) ? w0 : (blockIdx.z == 1) ? w1
                   : (blockIdx.z == 2) ? w2 : w3;
    __nv_bfloat16* Oh = g_wh[blockIdx.z];
    __nv_bfloat16* Ol = g_wl[blockIdx.z];

    __shared__ float t[32][33];
    int k0 = blockIdx.y * 32, n0 = blockIdx.x * 32;
    int tx = threadIdx.x, ty = threadIdx.y;
#pragma unroll
    for (int j = 0; j < 4; j++)
        t[ty + j * 8][tx] = W[(size_t)(k0 + ty + j * 8) * DIM + n0 + tx];
    __syncthreads();
#pragma unroll
    for (int j = 0; j < 4; j++) {
        float v = t[tx][ty + j * 8];
        __nv_bfloat16 h = __float2bfloat16(v);
        __nv_bfloat16 l = __float2bfloat16(v - __bfloat162float(h));
        size_t o = (size_t)(n0 + ty + j * 8) * DIM + k0 + tx;
        Oh[o] = h;
        Ol[o] = l;
    }
}

// ---------------- mma.sync bf16x3 GEMM -----------------------------------------
// C[3840,1536] = A @ W^T(stored [N][K]) + bias. 128x128 CTA tile, BK=32.
// 8 warps in 2x4; each warp 64x32 (4 mtiles x 4 ntiles of m16n8k16).
#define TS 40   // smem row stride (bf16) -> conflict-free LDS.32 fragments

__global__ __launch_bounds__(256, 2)
void hgemm(int asel, int wsel, const float* __restrict__ bias,
           float* __restrict__ Cout, int csel)
{
    const __nv_bfloat16* Agh = asel ? g_ah : g_xh;
    const __nv_bfloat16* Agl = asel ? g_al : g_xl;
    const __nv_bfloat16* Bgh = g_wh[wsel];
    const __nv_bfloat16* Bgl = g_wl[wsel];
    float* C = (csel == 0) ? g_q : (csel == 1) ? g_k : (csel == 2) ? g_v : Cout;

    __shared__ __nv_bfloat16 sAh[128 * TS], sAl[128 * TS];
    __shared__ __nv_bfloat16 sBh[128 * TS], sBl[128 * TS];

    int tid = threadIdx.x, wid = tid >> 5, lid = tid & 31;
    int wm = wid >> 2, wn = wid & 3;               // warp tile: 64m x 32n
    int g = lid >> 2, tg = lid & 3;
    int m0 = blockIdx.y * 128, n0 = blockIdx.x * 128;

    uint32_t uAh = smem_u32(sAh), uAl = smem_u32(sAl);
    uint32_t uBh = smem_u32(sBh), uBl = smem_u32(sBl);

    // copy map: 512 16B segments per tile; 2 per thread
    int r0 = tid >> 2, s0 = tid & 3;
    int r1 = (tid + 256) >> 2, s1 = tid & 3;
    uint32_t so0 = r0 * (TS * 2) + s0 * 16;
    uint32_t so1 = r1 * (TS * 2) + s1 * 16;

    float acc[4][4][4];
#pragma unroll
    for (int t = 0; t < 4; t++)
#pragma unroll
        for (int u = 0; u < 4; u++)
#pragma unroll
            for (int c = 0; c < 4; c++) acc[t][u][c] = 0.f;

    const __nv_bfloat16* Asm = sAh;  (void)Asm;

    for (int ch = 0; ch < DIM / 32; ch++) {
        size_t ga0 = (size_t)(m0 + r0) * DIM + ch * 32 + s0 * 8;
        size_t ga1 = (size_t)(m0 + r1) * DIM + ch * 32 + s1 * 8;
        size_t gb0 = (size_t)(n0 + r0) * DIM + ch * 32 + s0 * 8;
        size_t gb1 = (size_t)(n0 + r1) * DIM + ch * 32 + s1 * 8;
        cpasync16(uAh + so0, &Agh[ga0]);
        cpasync16(uAh + so1, &Agh[ga1]);
        cpasync16(uAl + so0, &Agl[ga0]);
        cpasync16(uAl + so1, &Agl[ga1]);
        cpasync16(uBh + so0, &Bgh[gb0]);
        cpasync16(uBh + so1, &Bgh[gb1]);
        cpasync16(uBl + so0, &Bgl[gb0]);
        cpasync16(uBl + so1, &Bgl[gb1]);
        CP_COMMIT();
        CP_WAIT0();
        __syncthreads();

#pragma unroll
        for (int ks = 0; ks < 2; ks++) {
            int kc = ks * 16 + tg * 2;   // even bf16 col -> 4B aligned
            uint32_t ah[4][4], bh[4][2];
#pragma unroll
            for (int t = 0; t < 4; t++) {
                int ra = wm * 64 + t * 16 + g;
                ah[t][0] = *(uint32_t*)&sAh[ra * TS + kc];
                ah[t][1] = *(uint32_t*)&sAh[(ra + 8) * TS + kc];
                ah[t][2] = *(uint32_t*)&sAh[ra * TS + kc + 8];
                ah[t][3] = *(uint32_t*)&sAh[(ra + 8) * TS + kc + 8];
            }
#pragma unroll
            for (int u = 0; u < 4; u++) {
                int rb = wn * 32 + u * 8 + g;
                bh[u][0] = *(uint32_t*)&sBh[rb * TS + kc];
                bh[u][1] = *(uint32_t*)&sBh[rb * TS + kc + 8];
            }
#pragma unroll
            for (int t = 0; t < 4; t++)
#pragma unroll
                for (int u = 0; u < 4; u++)
                    mma16816(acc[t][u][0], acc[t][u][1], acc[t][u][2], acc[t][u][3],
                             ah[t][0], ah[t][1], ah[t][2], ah[t][3],
                             bh[u][0], bh[u][1]);

            // Ah * Bl
#pragma unroll
            for (int u = 0; u < 4; u++) {
                int rb = wn * 32 + u * 8 + g;
                uint32_t bl0 = *(uint32_t*)&sBl[rb * TS + kc];
                uint32_t bl1 = *(uint32_t*)&sBl[rb * TS + kc + 8];
#pragma unroll
                for (int t = 0; t < 4; t++)
                    mma16816(acc[t][u][0], acc[t][u][1], acc[t][u][2], acc[t][u][3],
                             ah[t][0], ah[t][1], ah[t][2], ah[t][3], bl0, bl1);
            }
            // Al * Bh
#pragma unroll
            for (int t = 0; t < 4; t++) {
                int ra = wm * 64 + t * 16 + g;
                uint32_t al0 = *(uint32_t*)&sAl[ra * TS + kc];
                uint32_t al1 = *(uint32_t*)&sAl[(ra + 8) * TS + kc];
                uint32_t al2 = *(uint32_t*)&sAl[ra * TS + kc + 8];
                uint32_t al3 = *(uint32_t*)&sAl[(ra + 8) * TS + kc + 8];
#pragma unroll
                for (int u = 0; u < 4; u++)
                    mma16816(acc[t][u][0], acc[t][u][1], acc[t][u][2], acc[t][u][3],
                             al0, al1, al2, al3, bh[u][0], bh[u][1]);
            }
        }
        __syncthreads();
    }

    // epilogue: bias + store (float2 per fragment half-row)
#pragma unroll
    for (int t = 0; t < 4; t++) {
        int row = m0 + wm * 64 + t * 16 + g;
#pragma unroll
        for (int u = 0; u < 4; u++) {
            int col = n0 + wn * 32 + u * 8 + tg * 2;
            float2 bv = *(const float2*)&bias[col];
            float2 lo = make_float2(acc[t][u][0] + bv.x, acc[t][u][1] + bv.y);
            float2 hi = make_float2(acc[t][u][2] + bv.x, acc[t][u][3] + bv.y);
            *(float2*)&C[(size_t)row * DIM + col] = lo;
            *(float2*)&C[(size_t)(row + 8) * DIM + col] = hi;
        }
    }
}

// ---------------- RMSNorm + RoPE (in place on g_q / g_k) ----------------------
__global__ void normrope_kernel(const float* __restrict__ nqw,
                                const float* __restrict__ nkw,
                                const float* __restrict__ freqs)
{
    int s = blockIdx.x;
    bool isq = (blockIdx.y == 0);
    float* buf = (isq ? g_q : g_k) + (size_t)s * DIM;
    const float* w = isq ? nqw : nkw;
    float oscale = isq ? 0.08838834764831845f : 1.0f;

    __shared__ float row[DIM];
    __shared__ float red[8];

    int tid = threadIdx.x;
    float ss = 0.f;
    for (int i = tid; i < DIM; i += 256) {
        float v = buf[i];
        row[i] = v;
        ss += v * v;
    }
#pragma unroll
    for (int o = 16; o; o >>= 1) ss += __shfl_xor_sync(0xffffffff, ss, o);
    if ((tid & 31) == 0) red[tid >> 5] = ss;
    __syncthreads();
    if (tid < 8) {
        float t = red[tid];
#pragma unroll
        for (int o = 4; o; o >>= 1) t += __shfl_xor_sync(0xff, t, o);
        if (tid == 0) red[0] = t;
    }
    __syncthreads();
    float r = rsqrtf(red[0] / (float)DIM + 1e-6f);

    int fi = s / (HG * WG);
    int rem = s % (HG * WG);
    int hi = rem / WG;
    int wi = rem % WG;

    for (int p = tid; p < NH * 64; p += 256) {
        int h = p >> 6, c = p & 63;
        int pos = (c < D_F) ? fi : (c < D_FH) ? hi : wi;
        float ang = freqs[pos * 64 + c];
        float sn, cs;
        sincosf(ang, &sn, &cs);
        int j = h * HD + 2 * c;
        float y0 = row[j] * r * w[j];
        float y1 = row[j + 1] * r * w[j + 1];
        buf[j]     = (y0 * cs - y1 * sn) * oscale;
        buf[j + 1] = (y0 * sn + y1 * cs) * oscale;
    }
}

// ---------------- fp32 flash attention, f32x2 ----------------------------------
#define AT_BQ 128
#define AT_BK 64
#define PT_STRIDE 132

__global__ __launch_bounds__(256, 1)
void attn_kernel()
{
    extern __shared__ float sm[];
    float* Qs = sm;                       // 128*128   [d][q]
    float* Ks = Qs + 128 * 128;           // 128*64    [d][k]
    float* Vs = Ks + 128 * 64;            // 64*128    [k][d]
    float* Pt = Vs + 64 * 128;            // 64*132    [k][q]

    int tid = threadIdx.x;
    int h = blockIdx.y;
    int q0 = blockIdx.x * AT_BQ;
    int ty = tid >> 4, tx = tid & 15;

#pragma unroll
    for (int it = 0; it < 16; it++) {
        int idx = tid + it * 256;
        int r = idx & 127, d4 = idx >> 7;
        float4 v = *(const float4*)&g_q[(size_t)(q0 + r) * DIM + h * HD + d4 * 4];
        Qs[(d4 * 4 + 0) * 128 + r] = v.x;
        Qs[(d4 * 4 + 1) * 128 + r] = v.y;
        Qs[(d4 * 4 + 2) * 128 + r] = v.z;
        Qs[(d4 * 4 + 3) * 128 + r] = v.w;
    }

    u64 oacc[8][4];
#pragma unroll
    for (int i = 0; i < 8; i++)
#pragma unroll
        for (int j = 0; j < 4; j++) oacc[i][j] = 0ull;
    float m_run[8], l_run[8];
#pragma unroll
    for (int i = 0; i < 8; i++) { m_run[i] = -1e30f; l_run[i] = 0.f; }

    for (int kb = 0; kb < SEQ / AT_BK; kb++) {
        int k0 = kb * AT_BK;
        __syncthreads();

#pragma unroll
        for (int it = 0; it < 8; it++) {
            int idx = tid + it * 256;
            int r = idx & 63, d4 = idx >> 6;
            float4 v = *(const float4*)&g_k[(size_t)(k0 + r) * DIM + h * HD + d4 * 4];
            Ks[(d4 * 4 + 0) * 64 + r] = v.x;
            Ks[(d4 * 4 + 1) * 64 + r] = v.y;
            Ks[(d4 * 4 + 2) * 64 + r] = v.z;
            Ks[(d4 * 4 + 3) * 64 + r] = v.w;
        }
#pragma unroll
        for (int it = 0; it < 8; it++) {
            int idx = tid + it * 256;
            int r = idx >> 5, d4 = idx & 31;
            *(float4*)&Vs[r * 128 + d4 * 4] =
                *(const float4*)&g_v[(size_t)(k0 + r) * DIM + h * HD + d4 * 4];
        }
        __syncthreads();

        u64 sacc[8][2];
#pragma unroll
        for (int i = 0; i < 8; i++) { sacc[i][0] = 0ull; sacc[i][1] = 0ull; }
#pragma unroll 4
        for (int d = 0; d < 128; d++) {
            float4 a0 = *(float4*)&Qs[d * 128 + ty * 8];
            float4 a1 = *(float4*)&Qs[d * 128 + ty * 8 + 4];
            ulonglong2 bp = *(ulonglong2*)&Ks[d * 64 + tx * 4];
            float av[8] = {a0.x, a0.y, a0.z, a0.w, a1.x, a1.y, a1.z, a1.w};
#pragma unroll
            for (int i = 0; i < 8; i++) {
                u64 ad = dup2(av[i]);
                sacc[i][0] = fma2(ad, bp.x, sacc[i][0]);
                sacc[i][1] = fma2(ad, bp.y, sacc[i][1]);
            }
        }

        float p[8][4];
        float corr[8];
#pragma unroll
        for (int i = 0; i < 8; i++) {
            float2 s0 = unpk(sacc[i][0]);
            float2 s1 = unpk(sacc[i][1]);
            p[i][0] = s0.x; p[i][1] = s0.y; p[i][2] = s1.x; p[i][3] = s1.y;
            float mx = fmaxf(fmaxf(p[i][0], p[i][1]), fmaxf(p[i][2], p[i][3]));
#pragma unroll
            for (int o = 8; o; o >>= 1)
                mx = fmaxf(mx, __shfl_xor_sync(0xffffffffu, mx, o));
            float mnew = fmaxf(m_run[i], mx);
            corr[i] = __expf(m_run[i] - mnew);
            float ls = 0.f;
#pragma unroll
            for (int j = 0; j < 4; j++) {
                p[i][j] = __expf(p[i][j] - mnew);
                ls += p[i][j];
            }
#pragma unroll
            for (int o = 8; o; o >>= 1)
                ls += __shfl_xor_sync(0xffffffffu, ls, o);
            l_run[i] = l_run[i] * corr[i] + ls;
            m_run[i] = mnew;
        }
#pragma unroll
        for (int c = 0; c < 4; c++) {
            int j = tx * 4 + c;
            float4 lo = make_float4(p[0][c], p[1][c], p[2][c], p[3][c]);
            float4 hi = make_float4(p[4][c], p[5][c], p[6][c], p[7][c]);
            *(float4*)&Pt[j * PT_STRIDE + ty * 8] = lo;
            *(float4*)&Pt[j * PT_STRIDE + ty * 8 + 4] = hi;
        }
        __syncthreads();

#pragma unroll
        for (int i = 0; i < 8; i++) {
            u64 cd = dup2(corr[i]);
#pragma unroll
            for (int jp = 0; jp < 4; jp++) oacc[i][jp] = mul2(oacc[i][jp], cd);
        }
#pragma unroll 2
        for (int j = 0; j < AT_BK; j++) {
            float4 p0 = *(float4*)&Pt[j * PT_STRIDE + ty * 8];
            float4 p1 = *(float4*)&Pt[j * PT_STRIDE + ty * 8 + 4];
            ulonglong2 v0 = *(ulonglong2*)&Vs[j * 128 + tx * 8];
            ulonglong2 v1 = *(ulonglong2*)&Vs[j * 128 + tx * 8 + 4];
            float pv[8] = {p0.x, p0.y, p0.z, p0.w, p1.x, p1.y, p1.z, p1.w};
#pragma unroll
            for (int i = 0; i < 8; i++) {
                u64 ad = dup2(pv[i]);
                oacc[i][0] = fma2(ad, v0.x, oacc[i][0]);
                oacc[i][1] = fma2(ad, v0.y, oacc[i][1]);
                oacc[i][2] = fma2(ad, v1.x, oacc[i][2]);
                oacc[i][3] = fma2(ad, v1.y, oacc[i][3]);
            }
        }
    }

#pragma unroll
    for (int i = 0; i < 8; i++) {
        float inv = 1.0f / l_run[i];
        float2 c0 = unpk(oacc[i][0]);
        float2 c1 = unpk(oacc[i][1]);
        float2 c2 = unpk(oacc[i][2]);
        float2 c3 = unpk(oacc[i][3]);
        float4 lo = make_float4(c0.x * inv, c0.y * inv, c1.x * inv, c1.y * inv);
        float4 hi = make_float4(c2.x * inv, c2.y * inv, c3.x * inv, c3.y * inv);
        float* dst = &g_att[(size_t)(q0 + ty * 8 + i) * DIM + h * HD + tx * 8];
        *(float4*)&dst[0] = lo;
        *(float4*)&dst[4] = hi;
    }
}

// ---------------- launch ------------------------------------------------------
extern "C" void kernel_launch(void* const* d_in, const int* in_sizes, int n_in,
                              void* d_out, int out_size)
{
    const float* x    = (const float*)d_in[0];
    const float* q_w  = (const float*)d_in[1];
    const float* q_b  = (const float*)d_in[2];
    const float* k_w  = (const float*)d_in[3];
    const float* k_b  = (const float*)d_in[4];
    const float* v_w  = (const float*)d_in[5];
    const float* v_b  = (const float*)d_in[6];
    const float* o_w  = (const float*)d_in[7];
    const float* o_b  = (const float*)d_in[8];
    const float* nqw  = (const float*)d_in[9];
    const float* nkw  = (const float*)d_in[10];
    const float* freqs = (const float*)d_in[11];
    float* out = (float*)d_out;

    size_t asm_sz = (size_t)(128 * 128 + 128 * 64 + 64 * 128 + 64 * PT_STRIDE)
                    * sizeof(float);
    cudaFuncSetAttribute(attn_kernel, cudaFuncAttributeMaxDynamicSharedMemorySize,
                         (int)asm_sz);

    split_act<<<SEQ * DIM / 1024, 256>>>(x, 0);
    transpose_split<<<dim3(DIM / 32, DIM / 32, 4), dim3(32, 8)>>>(q_w, k_w, v_w, o_w);

    dim3 gg(DIM / 128, SEQ / 128);
    hgemm<<<gg, 256>>>(0, 0, q_b, nullptr, 0);
    hgemm<<<gg, 256>>>(0, 1, k_b, nullptr, 1);
    hgemm<<<gg, 256>>>(0, 2, v_b, nullptr, 2);

    normrope_kernel<<<dim3(SEQ, 2), 256>>>(nqw, nkw, freqs);

    attn_kernel<<<dim3(SEQ / AT_BQ, NH), 256, asm_sz>>>();

    split_act<<<SEQ * DIM / 1024, 256>>>(nullptr, 1);
    hgemm<<<gg, 256>>>(1, 3, o_b, out, 3);
}